// round 17
// baseline (speedup 1.0000x reference)
#include <cuda_runtime.h>
#include <cuda_fp16.h>
#include <cstdint>
#include <cmath>

// Problem constants
#define NN_  8192
#define DD_  768
#define HH1_ 512
#define HH2_ 256

// ---------------- device scratch (static globals: allocation-guard legal) ----
__device__ __half g_Ph [67108864];            // S (fp16) then P' (fp16) in place
__device__ __half g_Xh [NN_ * DD_];
__device__ __half g_Qh [NN_ * DD_];
__device__ __half g_Kh [NN_ * DD_];
__device__ __half g_Vt [DD_ * NN_];           // V^T  [768][8192]
__device__ __half g_Yh [NN_ * DD_];
__device__ __half g_H1h[NN_ * HH1_];
__device__ __half g_H2h[NN_ * HH2_];
__device__ float  g_G  [NN_];
__device__ __half g_WqT[DD_ * DD_];
__device__ __half g_WkT[DD_ * DD_];
__device__ __half g_WgT[DD_ * DD_];
__device__ __half g_W1aT[HH1_ * DD_];
__device__ __half g_W2aT[HH2_ * HH1_];
__device__ __half g_W1bT[HH1_ * DD_];
__device__ __half g_W2bT[HH2_ * HH1_];

// ---------------- math helpers ---------------------------------------------
__device__ __forceinline__ float gelu_exact(float x) {
    return 0.5f * x * (1.0f + erff(x * 0.70710678118654752440f));
}
__device__ __forceinline__ float softplus_(float x) {
    return fmaxf(x, 0.0f) + log1pf(expf(-fabsf(x)));
}
__device__ __forceinline__ void mma_f16(float* c, const unsigned* a, const unsigned* b) {
    asm volatile(
        "mma.sync.aligned.m16n8k16.row.col.f32.f16.f16.f32 "
        "{%0,%1,%2,%3}, {%4,%5,%6,%7}, {%8,%9}, {%0,%1,%2,%3};"
        : "+f"(c[0]), "+f"(c[1]), "+f"(c[2]), "+f"(c[3])
        : "r"(a[0]), "r"(a[1]), "r"(a[2]), "r"(a[3]), "r"(b[0]), "r"(b[1]));
}
__device__ __forceinline__ void ldsm_x4(unsigned& r0, unsigned& r1, unsigned& r2, unsigned& r3,
                                        unsigned addr) {
    asm volatile("ldmatrix.sync.aligned.m8n8.x4.shared.b16 {%0,%1,%2,%3}, [%4];"
                 : "=r"(r0), "=r"(r1), "=r"(r2), "=r"(r3) : "r"(addr));
}
__device__ __forceinline__ void cp_async16(unsigned dst, const void* src) {
    unsigned long long gsrc = __cvta_generic_to_global(src);
    asm volatile("cp.async.cg.shared.global [%0], [%1], 16;" :: "r"(dst), "l"(gsrc) : "memory");
}
__device__ __forceinline__ unsigned smem_addr(const void* p) {
    return (unsigned)__cvta_generic_to_shared(p);
}

// ---------------- fp32 -> fp16 elementwise ----------------------------------
__global__ void cvt_half_kernel(const float* __restrict__ in, __half* __restrict__ outp) {
    const int i = (blockIdx.x * 256 + threadIdx.x) * 4;
    float4 v = *(const float4*)(in + i);
    *(__half2*)(outp + i)     = __floats2half2_rn(v.x, v.y);
    *(__half2*)(outp + i + 2) = __floats2half2_rn(v.z, v.w);
}

// ---------------- fp32 [R][C] -> fp16 transposed [C][R] ----------------------
__global__ void cvtT_half_kernel(const float* __restrict__ in, __half* __restrict__ outp,
                                 int R, int C) {
    __shared__ float t[32][33];
    const int cb = blockIdx.x * 32, rb = blockIdx.y * 32;
    for (int i = threadIdx.y; i < 32; i += 8)
        t[i][threadIdx.x] = in[(size_t)(rb + i) * C + cb + threadIdx.x];
    __syncthreads();
    for (int i = threadIdx.y; i < 32; i += 8)
        outp[(size_t)(cb + i) * R + rb + threadIdx.x] = __float2half(t[threadIdx.x][i]);
}

// ============================================================================
// 128x128x16 FP16 tensor-core GEMM, all-TRANSB form, 6-stage cp.async pipeline,
// ldmatrix fragment loads.
// A: [M,K] half row-major (K-major); B: [Nn_total,K] half row-major (K-major).
// C = epi( scale * A @ B^T )
//   EPI 0: C = acc*scale
//   EPI 1: C = gelu(acc + bias[col])
//   EPI 2: C = addsrc[row,col] + gelu(acc + bias[col])    (addsrc fp32)
//   HOUT : C stored as __half (else float)
//   TSTORE: C stored transposed, C[col*M + row] (half only)
// Requires: M%128==0, Nn%128==0, K%16==0, K/16 >= NSTAGE-1.
// Smem: per stage A[128][12] uints (8 payload words + 4 pad) + B same.
// Pitch 12 words => ldmatrix phases cover all 32 banks (conflict-free).
// ============================================================================
template<int EPI, bool HOUT, bool TSTORE>
__global__ __launch_bounds__(256)
void hgemm(const __half* __restrict__ A, const __half* __restrict__ B,
           void* __restrict__ Cv, int M, int Nn, int K,
           const float* __restrict__ bias, const float* __restrict__ addsrc,
           float scale)
{
    constexpr int KT = 16, NSTAGE = 6;
    constexpr int TW = 128 * 12;              // words per (A or B) stage
    extern __shared__ unsigned sm[];
    unsigned* AsBase = sm;                    // [NSTAGE][128][12]
    unsigned* BsBase = sm + NSTAGE * TW;

    const int tid  = threadIdx.x;
    const int lane = tid & 31;
    const int warp = tid >> 5;
    const int warpM = (warp & 1) * 64;
    const int warpN = (warp >> 1) * 32;
    const int rowBase = blockIdx.y * 128, colBase = blockIdx.x * 128;

    // loader: one 16B chunk per matrix per thread: row = tid>>1, seg = tid&1
    const int ldRow = tid >> 1;
    const int ldSeg = tid & 1;
    const __half* gA = A + (size_t)(rowBase + ldRow) * K + ldSeg * 8;
    const __half* gB = B + (size_t)(colBase + ldRow) * K + ldSeg * 8;
    const unsigned stOff = (ldRow * 12 + ldSeg * 4) * 4;   // bytes

    auto load_tile = [&](int t, int s) {
        cp_async16(smem_addr(AsBase + s * TW) + stOff, gA + t * KT);
        cp_async16(smem_addr(BsBase + s * TW) + stOff, gB + t * KT);
    };

    // ldmatrix per-lane addresses (byte offsets within a stage)
    const unsigned aFragOff = ((warpM + (lane & 15)) * 12 + (lane >> 4) * 4) * 4;
    const unsigned bFragOff = ((warpN + (lane >> 4) * 8 + (lane & 7)) * 12
                               + ((lane >> 3) & 1) * 4) * 4;
    const unsigned aBaseS = smem_addr(AsBase);
    const unsigned bBaseS = smem_addr(BsBase);

    float acc[4][4][4];
#pragma unroll
    for (int i = 0; i < 4; i++)
#pragma unroll
        for (int j = 0; j < 4; j++)
#pragma unroll
            for (int q = 0; q < 4; q++) acc[i][j][q] = 0.0f;

    const int ntiles = K / KT;

#pragma unroll
    for (int s = 0; s < NSTAGE - 1; s++) {
        load_tile(s, s);
        asm volatile("cp.async.commit_group;" ::: "memory");
    }

    int stC = 0;               // compute stage for tile t
    int stL = NSTAGE - 1;      // load stage for tile t+NSTAGE-1

    for (int t = 0; t < ntiles; t++) {
        asm volatile("cp.async.wait_group %0;" :: "n"(NSTAGE - 2) : "memory");
        __syncthreads();

        // issue next tile's loads early (stage stL was freed at iteration t-1)
        const int tn = t + NSTAGE - 1;
        if (tn < ntiles) load_tile(tn, stL);
        asm volatile("cp.async.commit_group;" ::: "memory");

        const unsigned aSt = aBaseS + stC * (TW * 4) + aFragOff;
        const unsigned bSt = bBaseS + stC * (TW * 4) + bFragOff;

        unsigned af[4][4];
#pragma unroll
        for (int i = 0; i < 4; i++)
            ldsm_x4(af[i][0], af[i][1], af[i][2], af[i][3], aSt + i * (16 * 12 * 4));

        unsigned bf[4][2];
#pragma unroll
        for (int jp = 0; jp < 2; jp++)
            ldsm_x4(bf[2 * jp][0], bf[2 * jp][1], bf[2 * jp + 1][0], bf[2 * jp + 1][1],
                    bSt + jp * (16 * 12 * 4));

#pragma unroll
        for (int i = 0; i < 4; i++)
#pragma unroll
            for (int j = 0; j < 4; j++)
                mma_f16(acc[i][j], af[i], bf[j]);

        stC = (stC + 1 == NSTAGE) ? 0 : stC + 1;
        stL = (stL + 1 == NSTAGE) ? 0 : stL + 1;
    }

    // epilogue: fragment m16n8 -> c0,c1 at (r0, 2c), c2,c3 at (r0+8, 2c)
    float* Cf = (float*)Cv;
    __half* Ch = (__half*)Cv;
    const int r0 = lane >> 2;
    const int cc = (lane & 3) * 2;
#pragma unroll
    for (int i = 0; i < 4; i++) {
        const int gr = rowBase + warpM + i * 16 + r0;
#pragma unroll
        for (int j = 0; j < 4; j++) {
            const int gc = colBase + warpN + j * 8 + cc;
#pragma unroll
            for (int half_ = 0; half_ < 2; half_++) {
                const int row = gr + half_ * 8;
                float v0 = acc[i][j][half_ * 2 + 0] * scale;
                float v1 = acc[i][j][half_ * 2 + 1] * scale;
                if (EPI == 1) {
                    v0 = gelu_exact(v0 + bias[gc]);
                    v1 = gelu_exact(v1 + bias[gc + 1]);
                } else if (EPI == 2) {
                    const float* ap = addsrc + (size_t)row * Nn + gc;
                    v0 = ap[0] + gelu_exact(v0 + bias[gc]);
                    v1 = ap[1] + gelu_exact(v1 + bias[gc + 1]);
                }
                if (TSTORE) {
                    Ch[(size_t)gc * M + row]       = __float2half(v0);
                    Ch[(size_t)(gc + 1) * M + row] = __float2half(v1);
                } else if (HOUT) {
                    *(__half2*)(Ch + (size_t)row * Nn + gc) = __floats2half2_rn(v0, v1);
                } else {
                    *(float2*)(Cf + (size_t)row * Nn + gc) = make_float2(v0, v1);
                }
            }
        }
    }
}

// ---------------- NIG head final ---------------------------------------------
__global__ void head_final(const __half* __restrict__ H2, const float* __restrict__ Wh,
                           const float* __restrict__ bh, float* __restrict__ out,
                           int outOff, float* __restrict__ Gbuf,
                           const float* __restrict__ gamp, int N)
{
    const int warp = threadIdx.x >> 5, lane = threadIdx.x & 31;
    const int row = blockIdx.x * 8 + warp;

    float4 acc = make_float4(0.f, 0.f, 0.f, 0.f);
    const __half* h = H2 + (size_t)row * HH2_ + lane * 8;
#pragma unroll
    for (int i = 0; i < 8; i++) {
        float hv = __half2float(h[i]);
        float4 w = *(const float4*)&Wh[(lane * 8 + i) * 4];
        acc.x = fmaf(hv, w.x, acc.x);
        acc.y = fmaf(hv, w.y, acc.y);
        acc.z = fmaf(hv, w.z, acc.z);
        acc.w = fmaf(hv, w.w, acc.w);
    }
#pragma unroll
    for (int off = 16; off > 0; off >>= 1) {
        acc.x += __shfl_xor_sync(0xffffffffu, acc.x, off);
        acc.y += __shfl_xor_sync(0xffffffffu, acc.y, off);
        acc.z += __shfl_xor_sync(0xffffffffu, acc.z, off);
        acc.w += __shfl_xor_sync(0xffffffffu, acc.w, off);
    }
    if (lane == 0) {
        float mu = acc.x + bh[0];
        float v  = softplus_(acc.y + bh[1]) + 1e-6f;
        float a  = softplus_(acc.z + bh[2]) + 1.0f + 1e-6f;
        float b  = softplus_(acc.w + bh[3]) + 1e-6f;
        out[outOff + 0 * N + row] = mu;
        out[outOff + 1 * N + row] = v;
        out[outOff + 2 * N + row] = a;
        out[outOff + 3 * N + row] = b;
        if (Gbuf) {
            float u0  = b / fmaxf(a - 1.0f, 1e-8f);
            float sig = 1.0f / (1.0f + expf(-u0));
            Gbuf[row] = 1.0f - gamp[0] * sig;
        }
    }
}

// ---------------- fused softmax stats + gated rescale, fp16 in place ---------
// One block per row of the fp16 score matrix S (== P' buffer).
// Pass 1: m_i, Z, W. Pass 2 (L1-resident row): P'[i,j] = half(exp(S-m)*G_j*s_i),
// s_i = (G_i/Z)/max(G_i*W/Z, 1e-8).
__global__ void softmax_fused(__half* __restrict__ SP, const float* __restrict__ G, int N)
{
    const int row = blockIdx.x;
    __half* s = SP + (size_t)row * N;
    float m = -INFINITY, Z = 0.f, W = 0.f;
    for (int j = threadIdx.x * 4; j < N; j += 1024) {
        __half2 h0 = *(const __half2*)(s + j);
        __half2 h1 = *(const __half2*)(s + j + 2);
        float2 x0 = __half22float2(h0);
        float2 x1 = __half22float2(h1);
        float4 g = *(const float4*)(G + j);
        float xv[4] = {x0.x, x0.y, x1.x, x1.y};
        float gv[4] = {g.x, g.y, g.z, g.w};
#pragma unroll
        for (int q = 0; q < 4; q++) {
            float xx = xv[q];
            if (xx > m) {
                float e = expf(m - xx);
                Z *= e; W *= e; m = xx;
            }
            float pq = expf(xx - m);
            Z += pq; W = fmaf(pq, gv[q], W);
        }
    }
    __shared__ float sm[256], sZ[256], sW[256];
    sm[threadIdx.x] = m; sZ[threadIdx.x] = Z; sW[threadIdx.x] = W;
    __syncthreads();
    for (int off = 128; off > 0; off >>= 1) {
        if (threadIdx.x < off) {
            float m1 = sm[threadIdx.x],       Z1 = sZ[threadIdx.x],       W1 = sW[threadIdx.x];
            float m2 = sm[threadIdx.x + off], Z2 = sZ[threadIdx.x + off], W2 = sW[threadIdx.x + off];
            float mn = fmaxf(m1, m2);
            float e1 = expf(m1 - mn), e2 = expf(m2 - mn);
            sm[threadIdx.x] = mn;
            sZ[threadIdx.x] = Z1 * e1 + Z2 * e2;
            sW[threadIdx.x] = W1 * e1 + W2 * e2;
        }
        __syncthreads();
    }
    const float mF = sm[0], ZF = sZ[0], WF = sW[0];
    const float Gi = G[row];
    const float rowsum = Gi * WF / ZF;
    const float sc = (Gi / ZF) / fmaxf(rowsum, 1e-8f);

    for (int j = threadIdx.x * 4; j < N; j += 1024) {
        __half2 h0 = *(const __half2*)(s + j);
        __half2 h1 = *(const __half2*)(s + j + 2);
        float2 x0 = __half22float2(h0);
        float2 x1 = __half22float2(h1);
        float4 g = *(const float4*)(G + j);
        *(__half2*)(s + j)     = __floats2half2_rn(expf(x0.x - mF) * g.x * sc, expf(x0.y - mF) * g.y * sc);
        *(__half2*)(s + j + 2) = __floats2half2_rn(expf(x1.x - mF) * g.z * sc, expf(x1.y - mF) * g.w * sc);
    }
}

// ---------------- launcher ---------------------------------------------------
extern "C" void kernel_launch(void* const* d_in, const int* in_sizes, int n_in,
                              void* d_out, int out_size)
{
    (void)in_sizes; (void)n_in; (void)out_size;

    const float* X    = (const float*)d_in[0];
    const float* Wq   = (const float*)d_in[1];
    const float* Wk   = (const float*)d_in[2];
    const float* Wg   = (const float*)d_in[3];
    const float* bg   = (const float*)d_in[4];
    const float* gam  = (const float*)d_in[5];
    const float* ihW1 = (const float*)d_in[6];
    const float* ihb1 = (const float*)d_in[7];
    const float* ihW2 = (const float*)d_in[8];
    const float* ihb2 = (const float*)d_in[9];
    const float* ihWh = (const float*)d_in[10];
    const float* ihbh = (const float*)d_in[11];
    const float* fhW1 = (const float*)d_in[12];
    const float* fhb1 = (const float*)d_in[13];
    const float* fhW2 = (const float*)d_in[14];
    const float* fhb2 = (const float*)d_in[15];
    const float* fhWh = (const float*)d_in[16];
    const float* fhbh = (const float*)d_in[17];
    float* out = (float*)d_out;

    float *G;
    __half *Ph, *Xh, *Qh, *Kh, *Vt, *Yh, *H1h, *H2h;
    __half *WqT, *WkT, *WgT, *W1aT, *W2aT, *W1bT, *W2bT;
    cudaGetSymbolAddress((void**)&G,   g_G);
    cudaGetSymbolAddress((void**)&Ph,  g_Ph);
    cudaGetSymbolAddress((void**)&Xh,  g_Xh);
    cudaGetSymbolAddress((void**)&Qh,  g_Qh);
    cudaGetSymbolAddress((void**)&Kh,  g_Kh);
    cudaGetSymbolAddress((void**)&Vt,  g_Vt);
    cudaGetSymbolAddress((void**)&Yh,  g_Yh);
    cudaGetSymbolAddress((void**)&H1h, g_H1h);
    cudaGetSymbolAddress((void**)&H2h, g_H2h);
    cudaGetSymbolAddress((void**)&WqT, g_WqT);
    cudaGetSymbolAddress((void**)&WkT, g_WkT);
    cudaGetSymbolAddress((void**)&WgT, g_WgT);
    cudaGetSymbolAddress((void**)&W1aT, g_W1aT);
    cudaGetSymbolAddress((void**)&W2aT, g_W2aT);
    cudaGetSymbolAddress((void**)&W1bT, g_W1bT);
    cudaGetSymbolAddress((void**)&W2bT, g_W2bT);

    const int N = NN_, D = DD_, H1 = HH1_, H2 = HH2_;
    const float invSqrtD = 1.0f / sqrtf((float)D);

    constexpr int SMEM_H = 6 * 2 * 128 * 12 * 4;   // 73728 B
    cudaFuncSetAttribute(hgemm<0, true , false>, cudaFuncAttributeMaxDynamicSharedMemorySize, SMEM_H);
    cudaFuncSetAttribute(hgemm<0, true , true >, cudaFuncAttributeMaxDynamicSharedMemorySize, SMEM_H);
    cudaFuncSetAttribute(hgemm<1, true , false>, cudaFuncAttributeMaxDynamicSharedMemorySize, SMEM_H);
    cudaFuncSetAttribute(hgemm<2, true , false>, cudaFuncAttributeMaxDynamicSharedMemorySize, SMEM_H);

    // ---- fp16 conversions (X elementwise; weights transposed) ----
    cvt_half_kernel<<<(N * D) / 1024, 256>>>(X, Xh);
    dim3 tb(32, 8);
    cvtT_half_kernel<<<dim3(D / 32, D / 32), tb>>>(Wq, WqT, D, D);
    cvtT_half_kernel<<<dim3(D / 32, D / 32), tb>>>(Wk, WkT, D, D);
    cvtT_half_kernel<<<dim3(D / 32, D / 32), tb>>>(Wg, WgT, D, D);
    cvtT_half_kernel<<<dim3(H1 / 32, D / 32), tb>>>(ihW1, W1aT, D, H1);
    cvtT_half_kernel<<<dim3(H2 / 32, H1 / 32), tb>>>(ihW2, W2aT, H1, H2);
    cvtT_half_kernel<<<dim3(H1 / 32, D / 32), tb>>>(fhW1, W1bT, D, H1);
    cvtT_half_kernel<<<dim3(H2 / 32, H1 / 32), tb>>>(fhW2, W2bT, H1, H2);

    // ---- head 1 on X -> m0,v0,a0,b0 (out[0..4N)) and gate G ----
    hgemm<1, true, false><<<dim3(H1 / 128, N / 128), 256, SMEM_H>>>(Xh,  W1aT, H1h, N, H1, D,  ihb1, nullptr, 1.0f);
    hgemm<1, true, false><<<dim3(H2 / 128, N / 128), 256, SMEM_H>>>(H1h, W2aT, H2h, N, H2, H1, ihb2, nullptr, 1.0f);
    head_final<<<N / 8, 256>>>(H2h, ihWh, ihbh, out, 0, G, gam, N);

    // ---- projections: Qh, Kh row-major; V stored transposed (Vt) ----
    hgemm<0, true, false><<<dim3(D / 128, N / 128), 256, SMEM_H>>>(Xh, WqT, Qh, N, D, D, nullptr, nullptr, 1.0f);
    hgemm<0, true, false><<<dim3(D / 128, N / 128), 256, SMEM_H>>>(Xh, WkT, Kh, N, D, D, nullptr, nullptr, 1.0f);
    hgemm<0, true, true ><<<dim3(D / 128, N / 128), 256, SMEM_H>>>(Xh, WgT, Vt, N, D, D, nullptr, nullptr, 1.0f);

    // ---- S = Q K^T / sqrt(D)  (fp16, into P' buffer) ----
    hgemm<0, true, false><<<dim3(N / 128, N / 128), 256, SMEM_H>>>(Qh, Kh, Ph, N, N, D, nullptr, nullptr, invSqrtD);

    // ---- fused softmax stats + gated row normalization, fp16 in place ----
    softmax_fused<<<N, 256>>>(Ph, G, N);

    // ---- Y = X + gelu(P' @ V + bg)  (A=Ph [N,N], B=Vt [D][N] K-major) ----
    hgemm<2, true, false><<<dim3(D / 128, N / 128), 256, SMEM_H>>>(Ph, Vt, Yh, N, D, N, bg, X, 1.0f);

    // ---- head 2 on Y -> mu,v,al,be (out[4N..8N)) ----
    hgemm<1, true, false><<<dim3(H1 / 128, N / 128), 256, SMEM_H>>>(Yh,  W1bT, H1h, N, H1, D,  fhb1, nullptr, 1.0f);
    hgemm<1, true, false><<<dim3(H2 / 128, N / 128), 256, SMEM_H>>>(H1h, W2bT, H2h, N, H2, H1, fhb2, nullptr, 1.0f);
    head_final<<<N / 8, 256>>>(H2h, fhWh, fhbh, out, 4 * N, nullptr, gam, N);
}